// round 3
// baseline (speedup 1.0000x reference)
#include <cuda_runtime.h>
#include <math.h>

#define Bc 64
#define Sc 2048
#define Hc 512
#define Kc 1024
#define SCC 16
#define SCHUNK (Sc/SCC)   // 128

// Scratch (no allocations allowed in kernel_launch)
__device__ float g_q[Bc*Hc];            // 128 KB
__device__ float g_scores[Bc*Sc];       // 512 KB
__device__ float g_part[SCC*Bc*Kc];     // 4 MB
__device__ int   g_cnt[Bc];             // per-b completion counters (zero-init)

// tanh(x) = 1 - 2/(exp(2x)+1); __expf ~2ulp -> overall ~1e-6 error.
__device__ __forceinline__ float fast_tanhf(float x) {
    float e = __expf(2.0f * x);
    return 1.0f - __fdividef(2.0f, e + 1.0f);
}

#if defined(__CUDA_ARCH__) && (__CUDA_ARCH__ >= 900)
#define GRID_DEP_SYNC() cudaGridDependencySynchronize()
#else
#define GRID_DEP_SYNC()
#endif

// ---------------------------------------------------------------------------
// K1: q[b,h] = sum_e query[b,e] * W_q[h,e]
// grid (Hc/8, Bc), block 256 (warp per h).
// ---------------------------------------------------------------------------
__global__ void qproj_kernel(const float* __restrict__ query,
                             const float* __restrict__ Wq) {
    __shared__ float sq[Hc];
    const int b = blockIdx.y;
    const int t = threadIdx.x;
    sq[t]       = query[b*Hc + t];
    sq[t + 256] = query[b*Hc + t + 256];
    __syncthreads();

    const int warp = t >> 5, lane = t & 31;
    const int h = blockIdx.x * 8 + warp;
    const float4* wrow = (const float4*)(Wq + (size_t)h * Hc);
    float acc = 0.0f;
#pragma unroll
    for (int i = 0; i < 4; i++) {
        float4 w = wrow[lane + 32*i];
        int e = (lane + 32*i) * 4;
        acc = fmaf(w.x, sq[e],   acc);
        acc = fmaf(w.y, sq[e+1], acc);
        acc = fmaf(w.z, sq[e+2], acc);
        acc = fmaf(w.w, sq[e+3], acc);
    }
#pragma unroll
    for (int o = 16; o; o >>= 1) acc += __shfl_xor_sync(0xffffffffu, acc, o);
    if (lane == 0) g_q[b*Hc + h] = acc;
}

// ---------------------------------------------------------------------------
// K2: scores[b,s] = sum_h tanh(q[b,h] + pk[b,s,h]) * v[h]
// block 256 (8 warps), warp handles 2 rows -> 16 rows/block, 8192 blocks.
// ---------------------------------------------------------------------------
__global__ void score_kernel(const float* __restrict__ pk,
                             const float* __restrict__ v) {
    __shared__ float sq[Hc];
    __shared__ float sv[Hc];
    const int t = threadIdx.x;
    const int row0 = blockIdx.x * 16;
    const int b = row0 >> 11;               // S = 2048, blocks don't straddle b
    sv[t]       = v[t];                     // input: no dependency
    sv[t + 256] = v[t + 256];
    GRID_DEP_SYNC();                        // wait for qproj's g_q
    sq[t]       = g_q[b*Hc + t];
    sq[t + 256] = g_q[b*Hc + t + 256];
    __syncthreads();

    const int warp = t >> 5, lane = t & 31;
    const int rowA = row0 + warp*2;
    const int rowB = rowA + 1;
    const float4* pA = (const float4*)(pk + (size_t)rowA * Hc);
    const float4* pB = (const float4*)(pk + (size_t)rowB * Hc);
    float accA = 0.0f, accB = 0.0f;
#pragma unroll
    for (int i = 0; i < 4; i++) {
        float4 a = pA[lane + 32*i];
        float4 c = pB[lane + 32*i];
        int e = (lane + 32*i) * 4;
        float q0 = sq[e], q1 = sq[e+1], q2 = sq[e+2], q3 = sq[e+3];
        float v0 = sv[e], v1 = sv[e+1], v2 = sv[e+2], v3 = sv[e+3];
        accA = fmaf(fast_tanhf(a.x + q0), v0, accA);
        accA = fmaf(fast_tanhf(a.y + q1), v1, accA);
        accA = fmaf(fast_tanhf(a.z + q2), v2, accA);
        accA = fmaf(fast_tanhf(a.w + q3), v3, accA);
        accB = fmaf(fast_tanhf(c.x + q0), v0, accB);
        accB = fmaf(fast_tanhf(c.y + q1), v1, accB);
        accB = fmaf(fast_tanhf(c.z + q2), v2, accB);
        accB = fmaf(fast_tanhf(c.w + q3), v3, accB);
    }
#pragma unroll
    for (int o = 16; o; o >>= 1) {
        accA += __shfl_xor_sync(0xffffffffu, accA, o);
        accB += __shfl_xor_sync(0xffffffffu, accB, o);
    }
    if (lane == 0) {
        g_scores[rowA] = accA;
        g_scores[rowB] = accB;
    }
}

// ---------------------------------------------------------------------------
// K3 (fused): per-CTA softmax recompute + partial context + last-CTA reduce.
// grid (SCC, Bc), block 256. CTA (c,b):
//   - recomputes masked-softmax stats (max, sum) over all 2048 scores of b
//     (g_scores is L2-resident: 8 KB per CTA, negligible traffic)
//   - c==0 CTA writes alphas to d_out
//   - computes its 128-row weighted partial over encoder_hidden
//   - last CTA per b (threadfence reduction) sums 16 partials -> context
// Output deterministic: reduction order over c is fixed; only WHICH CTA
// performs it varies. Counter reset after use for graph replay.
// ---------------------------------------------------------------------------
__global__ void context_fused_kernel(const float* __restrict__ eh,
                                     const int* __restrict__ mask,
                                     float* __restrict__ alphas_out,
                                     float* __restrict__ ctx_out) {
    __shared__ float sa[SCHUNK];
    __shared__ float red[8];
    __shared__ bool  s_last;
    const int c = blockIdx.x;
    const int b = blockIdx.y;
    const int t = threadIdx.x;

    // pre-dependency work: mask is a kernel input
    int m[8];
#pragma unroll
    for (int i = 0; i < 8; i++) m[i] = mask[b*Sc + t + 256*i];

    GRID_DEP_SYNC();                        // wait for g_scores

    // --- softmax statistics over the full row b ---
    float vals[8];
    float mx = -INFINITY;
#pragma unroll
    for (int i = 0; i < 8; i++) {
        float x = g_scores[b*Sc + t + 256*i];
        if (m[i] == 0) x = -INFINITY;
        vals[i] = x;
        mx = fmaxf(mx, x);
    }
#pragma unroll
    for (int o = 16; o; o >>= 1) mx = fmaxf(mx, __shfl_xor_sync(0xffffffffu, mx, o));
    if ((t & 31) == 0) red[t >> 5] = mx;
    __syncthreads();
    mx = red[0];
#pragma unroll
    for (int i = 1; i < 8; i++) mx = fmaxf(mx, red[i]);

    float sum = 0.0f;
#pragma unroll
    for (int i = 0; i < 8; i++) {
        vals[i] = __expf(vals[i] - mx);
        sum += vals[i];
    }
#pragma unroll
    for (int o = 16; o; o >>= 1) sum += __shfl_xor_sync(0xffffffffu, sum, o);
    __syncthreads();
    if ((t & 31) == 0) red[t >> 5] = sum;
    __syncthreads();
    float tot = red[0];
#pragma unroll
    for (int i = 1; i < 8; i++) tot += red[i];
    const float inv = 1.0f / tot;

    // c==0 CTA publishes alphas to the output
    if (c == 0) {
#pragma unroll
        for (int i = 0; i < 8; i++)
            alphas_out[b*Sc + t + 256*i] = vals[i] * inv;
    }

    // this CTA's 128 alphas into smem (vals[] layout: s = t + 256*i)
    {
        int i = (c * SCHUNK) / 256;         // which vals-slot holds our chunk
        int base_t = (c * SCHUNK) % 256;    // 0 or 128
        if (t >= base_t && t < base_t + SCHUNK)
            sa[t - base_t] = vals[i] * inv;
    }
    __syncthreads();

    // --- weighted partial over encoder_hidden rows [c*128, c*128+128) ---
    const float4* base = (const float4*)(eh + ((size_t)(b*Sc + c*SCHUNK)) * Kc) + t;
    float4 acc = make_float4(0.f, 0.f, 0.f, 0.f);
#pragma unroll 8
    for (int s = 0; s < SCHUNK; s++) {
        float a = sa[s];
        float4 vv = base[(size_t)s * (Kc/4)];
        acc.x = fmaf(a, vv.x, acc.x);
        acc.y = fmaf(a, vv.y, acc.y);
        acc.z = fmaf(a, vv.z, acc.z);
        acc.w = fmaf(a, vv.w, acc.w);
    }
    ((float4*)g_part)[((size_t)c*Bc + b) * (Kc/4) + t] = acc;

    // --- last CTA per b reduces the 16 partials ---
    __syncthreads();
    if (t == 0) {
        __threadfence();                    // partials visible before count
        int prev = atomicAdd(&g_cnt[b], 1);
        s_last = (prev == SCC - 1);
    }
    __syncthreads();
    if (s_last) {
        __threadfence();                    // acquire: see all partials
        float4 r = make_float4(0.f, 0.f, 0.f, 0.f);
#pragma unroll
        for (int cc = 0; cc < SCC; cc++) {
            float4 p = ((const float4*)g_part)[((size_t)cc*Bc + b) * (Kc/4) + t];
            r.x += p.x; r.y += p.y; r.z += p.z; r.w += p.w;
        }
        ((float4*)ctx_out)[(size_t)b * (Kc/4) + t] = r;
        if (t == 0) g_cnt[b] = 0;           // reset for next graph replay
    }
}

// ---------------------------------------------------------------------------
template <typename K, typename... Args>
static inline void launch_pdl(K kernel, dim3 grid, dim3 block, Args... args) {
    cudaLaunchAttribute attr[1];
    attr[0].id = cudaLaunchAttributeProgrammaticStreamSerialization;
    attr[0].val.programmaticStreamSerializationAllowed = 1;
    cudaLaunchConfig_t cfg;
    cfg.gridDim = grid;
    cfg.blockDim = block;
    cfg.dynamicSmemBytes = 0;
    cfg.stream = 0;
    cfg.attrs = attr;
    cfg.numAttrs = 1;
    cudaLaunchKernelEx(&cfg, kernel, args...);
}

extern "C" void kernel_launch(void* const* d_in, const int* in_sizes, int n_in,
                              void* d_out, int out_size) {
    const float* query    = (const float*)d_in[0]; // (B,1,H)
    const float* proj_key = (const float*)d_in[1]; // (B,S,H)
    const float* enc      = (const float*)d_in[2]; // (B,S,K)
    const int*   mask     = (const int*)  d_in[3]; // (B,1,S)
    const float* Wq       = (const float*)d_in[4]; // (H,H)
    const float* v        = (const float*)d_in[5]; // (H,)

    float* ctx    = (float*)d_out;              // (B,1,K)
    float* alphas = (float*)d_out + Bc*Kc;      // (B,1,S)

    qproj_kernel<<<dim3(Hc/8, Bc), 256>>>(query, Wq);
    launch_pdl(score_kernel,         dim3((Bc*Sc)/16), dim3(256), proj_key, v);
    launch_pdl(context_fused_kernel, dim3(SCC, Bc),    dim3(256), enc, mask,
               alphas, ctx);
}

// round 4
// speedup vs baseline: 1.0204x; 1.0204x over previous
#include <cuda_runtime.h>
#include <math.h>

#define Bc 64
#define Sc 2048
#define Hc 512
#define Kc 1024
#define SCC 16
#define SCHUNK (Sc/SCC)   // 128
#define QB 16              // query rows per qproj CTA

// Scratch (no allocations allowed in kernel_launch)
__device__ float g_q[Bc*Hc];            // 128 KB
__device__ float g_scores[Bc*Sc];       // 512 KB
__device__ float g_part[SCC*Bc*Kc];     // 4 MB

// tanh(x) = 1 - 2/(exp(2x)+1); __expf ~2ulp -> overall ~1e-6 error.
__device__ __forceinline__ float fast_tanhf(float x) {
    float e = __expf(2.0f * x);
    return 1.0f - __fdividef(2.0f, e + 1.0f);
}

#if defined(__CUDA_ARCH__) && (__CUDA_ARCH__ >= 900)
#define GRID_DEP_SYNC() cudaGridDependencySynchronize()
#else
#define GRID_DEP_SYNC()
#endif

// ---------------------------------------------------------------------------
// K1: q[b,h] = sum_e query[b,e] * W_q[h,e]
// grid (Hc/8, Bc/QB) = (64, 4), block 256 (8 warps).
// Warp w keeps W_q row (h = bx*8+w) in registers and dots it against QB=16
// query rows staged in smem -> W_q L2 traffic 64MB -> 4MB vs old layout.
// ---------------------------------------------------------------------------
__global__ void qproj_kernel(const float* __restrict__ query,
                             const float* __restrict__ Wq) {
    __shared__ float sq[QB][Hc];            // 32 KB
    const int t = threadIdx.x;
    const int warp = t >> 5, lane = t & 31;
    const int h  = blockIdx.x * 8 + warp;
    const int b0 = blockIdx.y * QB;

    // W row -> registers (lane owns elements e = (lane+32i)*4 .. +3)
    const float4* wrow = (const float4*)(Wq + (size_t)h * Hc);
    float4 w0 = wrow[lane];
    float4 w1 = wrow[lane + 32];
    float4 w2 = wrow[lane + 64];
    float4 w3 = wrow[lane + 96];

    // stage QB query rows (QB*Hc/4 = 2048 float4, 8 per thread)
    {
        const float4* qsrc = (const float4*)(query + (size_t)b0 * Hc);
        float4* qdst = (float4*)&sq[0][0];
#pragma unroll
        for (int j = 0; j < (QB*Hc/4)/256; j++)
            qdst[t + 256*j] = qsrc[t + 256*j];
    }
    __syncthreads();

#pragma unroll
    for (int bb = 0; bb < QB; bb++) {
        const float* qr = sq[bb];
        int e0 = lane*4, e1 = (lane+32)*4, e2 = (lane+64)*4, e3 = (lane+96)*4;
        float acc;
        acc = w0.x*qr[e0]   + w0.y*qr[e0+1] + w0.z*qr[e0+2] + w0.w*qr[e0+3];
        acc = fmaf(w1.x, qr[e1], acc); acc = fmaf(w1.y, qr[e1+1], acc);
        acc = fmaf(w1.z, qr[e1+2], acc); acc = fmaf(w1.w, qr[e1+3], acc);
        acc = fmaf(w2.x, qr[e2], acc); acc = fmaf(w2.y, qr[e2+1], acc);
        acc = fmaf(w2.z, qr[e2+2], acc); acc = fmaf(w2.w, qr[e2+3], acc);
        acc = fmaf(w3.x, qr[e3], acc); acc = fmaf(w3.y, qr[e3+1], acc);
        acc = fmaf(w3.z, qr[e3+2], acc); acc = fmaf(w3.w, qr[e3+3], acc);
#pragma unroll
        for (int o = 16; o; o >>= 1) acc += __shfl_xor_sync(0xffffffffu, acc, o);
        if (lane == 0) g_q[(b0 + bb)*Hc + h] = acc;
    }
}

// ---------------------------------------------------------------------------
// K2: scores[b,s] = sum_h tanh(q[b,h] + pk[b,s,h]) * v[h]
// block 256 (8 warps), warp handles 2 rows -> 16 rows/block, 8192 blocks.
// ---------------------------------------------------------------------------
__global__ void score_kernel(const float* __restrict__ pk,
                             const float* __restrict__ v) {
    __shared__ float sq[Hc];
    __shared__ float sv[Hc];
    const int t = threadIdx.x;
    const int row0 = blockIdx.x * 16;
    const int b = row0 >> 11;               // S = 2048, blocks don't straddle b
    sv[t]       = v[t];                     // input: no dependency
    sv[t + 256] = v[t + 256];
    GRID_DEP_SYNC();                        // wait for qproj's g_q
    sq[t]       = g_q[b*Hc + t];
    sq[t + 256] = g_q[b*Hc + t + 256];
    __syncthreads();

    const int warp = t >> 5, lane = t & 31;
    const int rowA = row0 + warp*2;
    const int rowB = rowA + 1;
    const float4* pA = (const float4*)(pk + (size_t)rowA * Hc);
    const float4* pB = (const float4*)(pk + (size_t)rowB * Hc);
    float accA = 0.0f, accB = 0.0f;
#pragma unroll
    for (int i = 0; i < 4; i++) {
        float4 a = pA[lane + 32*i];
        float4 c = pB[lane + 32*i];
        int e = (lane + 32*i) * 4;
        float q0 = sq[e], q1 = sq[e+1], q2 = sq[e+2], q3 = sq[e+3];
        float v0 = sv[e], v1 = sv[e+1], v2 = sv[e+2], v3 = sv[e+3];
        accA = fmaf(fast_tanhf(a.x + q0), v0, accA);
        accA = fmaf(fast_tanhf(a.y + q1), v1, accA);
        accA = fmaf(fast_tanhf(a.z + q2), v2, accA);
        accA = fmaf(fast_tanhf(a.w + q3), v3, accA);
        accB = fmaf(fast_tanhf(c.x + q0), v0, accB);
        accB = fmaf(fast_tanhf(c.y + q1), v1, accB);
        accB = fmaf(fast_tanhf(c.z + q2), v2, accB);
        accB = fmaf(fast_tanhf(c.w + q3), v3, accB);
    }
#pragma unroll
    for (int o = 16; o; o >>= 1) {
        accA += __shfl_xor_sync(0xffffffffu, accA, o);
        accB += __shfl_xor_sync(0xffffffffu, accB, o);
    }
    if (lane == 0) {
        g_scores[rowA] = accA;
        g_scores[rowB] = accB;
    }
}

// ---------------------------------------------------------------------------
// K3: masked softmax over s for each b. grid Bc, block 256, 8 values/thread.
// ---------------------------------------------------------------------------
__global__ void softmax_kernel(const int* __restrict__ mask,
                               float* __restrict__ alphas_out) {
    const int b = blockIdx.x, t = threadIdx.x;
    __shared__ float red[8];

    int m[8];
#pragma unroll
    for (int i = 0; i < 8; i++) m[i] = mask[b*Sc + t + 256*i];

    GRID_DEP_SYNC();                        // wait for g_scores

    float vals[8];
    float mx = -INFINITY;
#pragma unroll
    for (int i = 0; i < 8; i++) {
        float x = g_scores[b*Sc + t + 256*i];
        if (m[i] == 0) x = -INFINITY;
        vals[i] = x;
        mx = fmaxf(mx, x);
    }
#pragma unroll
    for (int o = 16; o; o >>= 1) mx = fmaxf(mx, __shfl_xor_sync(0xffffffffu, mx, o));
    if ((t & 31) == 0) red[t >> 5] = mx;
    __syncthreads();
    mx = red[0];
#pragma unroll
    for (int i = 1; i < 8; i++) mx = fmaxf(mx, red[i]);

    float sum = 0.0f;
#pragma unroll
    for (int i = 0; i < 8; i++) {
        float e = __expf(vals[i] - mx);
        vals[i] = e;
        sum += e;
    }
#pragma unroll
    for (int o = 16; o; o >>= 1) sum += __shfl_xor_sync(0xffffffffu, sum, o);
    __syncthreads();
    if ((t & 31) == 0) red[t >> 5] = sum;
    __syncthreads();
    float tot = red[0];
#pragma unroll
    for (int i = 1; i < 8; i++) tot += red[i];
    float inv = 1.0f / tot;
#pragma unroll
    for (int i = 0; i < 8; i++)
        alphas_out[b*Sc + t + 256*i] = vals[i] * inv;
}

// ---------------------------------------------------------------------------
// K4: partial context. grid (SCC, Bc), block 256.
// Thread t owns float4 k-slot t (256 float4 = full K). Coalesced 4 KB rows.
// ---------------------------------------------------------------------------
__global__ void context_partial_kernel(const float* __restrict__ eh,
                                       const float* __restrict__ alphas) {
    __shared__ float sa[SCHUNK];
    const int c = blockIdx.x;
    const int b = blockIdx.y;
    const int t = threadIdx.x;

    GRID_DEP_SYNC();                        // wait for alphas (softmax output)
    if (t < SCHUNK) sa[t] = alphas[b*Sc + c*SCHUNK + t];
    __syncthreads();

    const float4* base = (const float4*)(eh + ((size_t)(b*Sc + c*SCHUNK)) * Kc) + t;
    float4 acc = make_float4(0.f, 0.f, 0.f, 0.f);
#pragma unroll 8
    for (int s = 0; s < SCHUNK; s++) {
        float a = sa[s];
        float4 vv = base[(size_t)s * (Kc/4)];
        acc.x = fmaf(a, vv.x, acc.x);
        acc.y = fmaf(a, vv.y, acc.y);
        acc.z = fmaf(a, vv.z, acc.z);
        acc.w = fmaf(a, vv.w, acc.w);
    }
    ((float4*)g_part)[((size_t)c*Bc + b) * (Kc/4) + t] = acc;
}

// ---------------------------------------------------------------------------
// K5: reduce 16 partials -> context. grid Bc, block 256 (float4 per thread).
// ---------------------------------------------------------------------------
__global__ void context_reduce_kernel(float* __restrict__ ctx_out) {
    const int b = blockIdx.x, t = threadIdx.x;
    GRID_DEP_SYNC();                        // wait for g_part
    float4 acc = make_float4(0.f, 0.f, 0.f, 0.f);
#pragma unroll
    for (int c = 0; c < SCC; c++) {
        float4 v = ((const float4*)g_part)[((size_t)c*Bc + b) * (Kc/4) + t];
        acc.x += v.x; acc.y += v.y; acc.z += v.z; acc.w += v.w;
    }
    ((float4*)ctx_out)[(size_t)b * (Kc/4) + t] = acc;
}

// ---------------------------------------------------------------------------
template <typename K, typename... Args>
static inline void launch_pdl(K kernel, dim3 grid, dim3 block, Args... args) {
    cudaLaunchAttribute attr[1];
    attr[0].id = cudaLaunchAttributeProgrammaticStreamSerialization;
    attr[0].val.programmaticStreamSerializationAllowed = 1;
    cudaLaunchConfig_t cfg;
    cfg.gridDim = grid;
    cfg.blockDim = block;
    cfg.dynamicSmemBytes = 0;
    cfg.stream = 0;
    cfg.attrs = attr;
    cfg.numAttrs = 1;
    cudaLaunchKernelEx(&cfg, kernel, args...);
}

extern "C" void kernel_launch(void* const* d_in, const int* in_sizes, int n_in,
                              void* d_out, int out_size) {
    const float* query    = (const float*)d_in[0]; // (B,1,H)
    const float* proj_key = (const float*)d_in[1]; // (B,S,H)
    const float* enc      = (const float*)d_in[2]; // (B,S,K)
    const int*   mask     = (const int*)  d_in[3]; // (B,1,S)
    const float* Wq       = (const float*)d_in[4]; // (H,H)
    const float* v        = (const float*)d_in[5]; // (H,)

    float* ctx    = (float*)d_out;              // (B,1,K)
    float* alphas = (float*)d_out + Bc*Kc;      // (B,1,S)

    qproj_kernel<<<dim3(Hc/8, Bc/QB), 256>>>(query, Wq);
    launch_pdl(score_kernel,           dim3((Bc*Sc)/16), dim3(256), proj_key, v);
    launch_pdl(softmax_kernel,         dim3(Bc),         dim3(256), mask, alphas);
    launch_pdl(context_partial_kernel, dim3(SCC, Bc),    dim3(256), enc, (const float*)alphas);
    launch_pdl(context_reduce_kernel,  dim3(Bc),         dim3(256), ctx);
}